// round 8
// baseline (speedup 1.0000x reference)
#include <cuda_runtime.h>

// Problem constants (fixed by reference setup_inputs)
#define B 8
#define N 256
#define D 128
#define D4 (D / 4)        // 32 float4 per feature row
#define CG 16             // column-groups per batch (grid = B*CG = 128 blocks)
#define CPB (D4 / CG)     // 2 float4 columns per block
#define NGS 128           // node-groups (threads per column)
#define NPT (N / NGS)     // 2 nodes per thread

__device__ __forceinline__ float4 f4add(float4 a, float4 b) {
    return make_float4(a.x + b.x, a.y + b.y, a.z + b.z, a.w + b.w);
}

// Single fused kernel, one __syncthreads, 128 CTAs (one wave, 128 SMs).
// Block (b, cg) owns 2 float4 columns of batch b.
// Thread layout: c = tid&1 (column), ng = tid>>1 (0..127). Warp w holds
// ngs [16w, 16w+16) for both columns.
// Path: 2 loads -> store first output half immediately (independent of S)
//       -> 4-shfl warp butterfly over ng -> 256B smem -> 1 barrier
//       -> 8-way cross-warp sum -> store second half (streaming).
__global__ void __launch_bounds__(256, 1)
fused_kernel(const float4* __restrict__ x, float4* __restrict__ out)
{
    __shared__ float4 part[8][CPB];   // [warp][col-in-block]

    const int blk = blockIdx.x;
    const int b   = blk >> 4;              // / CG
    const int cg  = blk & (CG - 1);

    const int c    = threadIdx.x & (CPB - 1);
    const int ng   = threadIdx.x >> 1;
    const int lane = threadIdx.x & 31;
    const int w    = threadIdx.x >> 5;
    const int col  = cg * CPB + c;

    const float4* xb = x + (size_t)b * N * D4;

    // Load NPT nodes for this column; accumulate partial sum.
    float4 v[NPT];
    float4 acc = make_float4(0.f, 0.f, 0.f, 0.f);
    #pragma unroll
    for (int k = 0; k < NPT; ++k) {
        const int n = ng + NGS * k;
        v[k] = xb[n * D4 + col];
        acc = f4add(acc, v[k]);
    }

    const float c1 = 255.0f / 256.0f;
    const float c2 = 1.0f / 256.0f;

    // First half of output does NOT depend on the sum — drain it now,
    // overlapping with the reduction below.
    #pragma unroll
    for (int k = 0; k < NPT; ++k) {
        const int n = ng + NGS * k;
        float4 o1;
        o1.x = v[k].x * c1; o1.y = v[k].y * c1;
        o1.z = v[k].z * c1; o1.w = v[k].w * c1;
        __stcs(&out[((size_t)(b * N + n)) * (2 * D4) + col], o1);
    }

    // Warp butterfly over the 16 node-groups in this warp (tid bits 1..4).
    #pragma unroll
    for (int m = 2; m < 32; m <<= 1) {
        acc.x += __shfl_xor_sync(0xffffffffu, acc.x, m);
        acc.y += __shfl_xor_sync(0xffffffffu, acc.y, m);
        acc.z += __shfl_xor_sync(0xffffffffu, acc.z, m);
        acc.w += __shfl_xor_sync(0xffffffffu, acc.w, m);
    }
    if (lane < CPB) part[w][c] = acc;     // lanes 0..1 carry c = 0..1
    __syncthreads();

    // Cross-warp combine: 8 broadcast LDS.128 + adds.
    float4 s = part[0][c];
    #pragma unroll
    for (int ww = 1; ww < 8; ++ww) s = f4add(s, part[ww][c]);

    // Second half: (S - x) / N, streaming stores (write-once data).
    #pragma unroll
    for (int k = 0; k < NPT; ++k) {
        const int n = ng + NGS * k;
        float4 o2;
        o2.x = (s.x - v[k].x) * c2; o2.y = (s.y - v[k].y) * c2;
        o2.z = (s.z - v[k].z) * c2; o2.w = (s.w - v[k].w) * c2;
        __stcs(&out[((size_t)(b * N + n)) * (2 * D4) + D4 + col], o2);
    }
}

extern "C" void kernel_launch(void* const* d_in, const int* in_sizes, int n_in,
                              void* d_out, int out_size)
{
    const float4* x = (const float4*)d_in[0];   // [B, N, D] fp32
    float4* out = (float4*)d_out;               // [B, N, 2D] fp32
    (void)in_sizes; (void)n_in; (void)out_size;

    fused_kernel<<<B * CG, NGS * CPB>>>(x, out);
}

// round 9
// speedup vs baseline: 1.0299x; 1.0299x over previous
#include <cuda_runtime.h>

// Problem constants (fixed by reference setup_inputs)
#define B 8
#define N 256
#define D 128
#define D4 (D / 4)       // 32 float4 per feature row
#define CG 8             // column-groups per batch (grid = B*CG = 64 blocks)
#define CPB (D4 / CG)    // 4 float4 columns per block
#define NGS 64           // node-groups (threads per column)
#define NPT (N / NGS)    // 4 nodes per thread

__device__ __forceinline__ float4 f4add(float4 a, float4 b) {
    return make_float4(a.x + b.x, a.y + b.y, a.z + b.z, a.w + b.w);
}

// Single fused kernel, one __syncthreads (best-measured R4 configuration;
// R5's __stcs + 128-CTA grid regressed wall time and are reverted).
// Block (b, cg) owns 4 float4 columns of batch b.
// Thread layout: c = tid&3 (column, low bits -> 64B coalesced chunks),
//                ng = tid>>2. Warp w holds ngs [8w, 8w+8).
// Path: 4 loads -> store first output half immediately (independent of S)
//       -> 3-shfl warp butterfly over ng -> 512B smem -> 1 barrier
//       -> 8-way cross-warp tree sum -> store second half.
__global__ void __launch_bounds__(256, 1)
fused_kernel(const float4* __restrict__ x, float4* __restrict__ out)
{
    __shared__ float4 part[8][CPB];   // [warp][col-in-block]

    const int blk = blockIdx.x;
    const int b   = blk >> 3;
    const int cg  = blk & (CG - 1);

    const int c    = threadIdx.x & (CPB - 1);
    const int ng   = threadIdx.x >> 2;
    const int lane = threadIdx.x & 31;
    const int w    = threadIdx.x >> 5;
    const int col  = cg * CPB + c;

    const float4* xb = x + (size_t)b * N * D4;

    // Load NPT nodes for this column; accumulate partial sum.
    float4 v[NPT];
    float4 acc = make_float4(0.f, 0.f, 0.f, 0.f);
    #pragma unroll
    for (int k = 0; k < NPT; ++k) {
        const int n = ng + NGS * k;
        v[k] = xb[n * D4 + col];
        acc = f4add(acc, v[k]);
    }

    const float c1 = 255.0f / 256.0f;
    const float c2 = 1.0f / 256.0f;

    // First half of output does NOT depend on the sum — drain it now,
    // overlapping the writes with the reduction below.
    #pragma unroll
    for (int k = 0; k < NPT; ++k) {
        const int n = ng + NGS * k;
        float4 o1;
        o1.x = v[k].x * c1; o1.y = v[k].y * c1;
        o1.z = v[k].z * c1; o1.w = v[k].w * c1;
        out[((size_t)(b * N + n)) * (2 * D4) + col] = o1;
    }

    // Warp butterfly over the 8 node-groups inside this warp
    // (tid bits 2..4 vary ng while sharing column c).
    #pragma unroll
    for (int m = 4; m < 32; m <<= 1) {
        acc.x += __shfl_xor_sync(0xffffffffu, acc.x, m);
        acc.y += __shfl_xor_sync(0xffffffffu, acc.y, m);
        acc.z += __shfl_xor_sync(0xffffffffu, acc.z, m);
        acc.w += __shfl_xor_sync(0xffffffffu, acc.w, m);
    }
    if (lane < CPB) part[w][c] = acc;     // lanes 0..3 carry c = 0..3
    __syncthreads();

    // Cross-warp combine: load all 8 partials first (pipelined LDS.128),
    // then pairwise tree-add (depth 3) — shorter dependency chain than a
    // serial load-add chain.
    float4 p0 = part[0][c], p1 = part[1][c], p2 = part[2][c], p3 = part[3][c];
    float4 p4 = part[4][c], p5 = part[5][c], p6 = part[6][c], p7 = part[7][c];
    p0 = f4add(p0, p1); p2 = f4add(p2, p3);
    p4 = f4add(p4, p5); p6 = f4add(p6, p7);
    p0 = f4add(p0, p2); p4 = f4add(p4, p6);
    const float4 s = f4add(p0, p4);

    // Second half: (S - x) / N, default (write-back) stores.
    #pragma unroll
    for (int k = 0; k < NPT; ++k) {
        const int n = ng + NGS * k;
        float4 o2;
        o2.x = (s.x - v[k].x) * c2; o2.y = (s.y - v[k].y) * c2;
        o2.z = (s.z - v[k].z) * c2; o2.w = (s.w - v[k].w) * c2;
        out[((size_t)(b * N + n)) * (2 * D4) + D4 + col] = o2;
    }
}

extern "C" void kernel_launch(void* const* d_in, const int* in_sizes, int n_in,
                              void* d_out, int out_size)
{
    const float4* x = (const float4*)d_in[0];   // [B, N, D] fp32
    float4* out = (float4*)d_out;               // [B, N, 2D] fp32
    (void)in_sizes; (void)n_in; (void)out_size;

    fused_kernel<<<B * CG, NGS * CPB>>>(x, out);
}